// round 6
// baseline (speedup 1.0000x reference)
#include <cuda_runtime.h>
#include <cuda_bf16.h>
#include <cstdint>

#define IH 400
#define IW 400
#define NPIX 160000
#define F1 128
#define F2 64
#define F3 8

// A tile: 64 rows (pixels) x 128 k (bf16), row padded to 272B (conflict-free ldmatrix)
#define AROW 272
#define OFF_AH  0
#define OFF_AL  17408
#define OFF_H2S 34816            // 4 warps x 16px x 65 f32 = 16640
#define OFF_B1S 51456
#define OFF_B2S 51968
#define OFF_B3S 52224
#define OFF_W3S 52256
#define SMEM_BYTES 54304

// Pre-packed weight fragments (uint4 = {bh0,bh1,bl0,bl1} per lane)
__device__ uint4 g_B1f[3 * 8 * 16 * 32];   // [chunk][kt][ni][lane]
__device__ uint4 g_W2f[8 * 8 * 32];        // [kt][ni2][lane]

// ---------------- helpers ----------------
__device__ __forceinline__ uint32_t smem_u32(const void* p) {
    uint32_t a;
    asm("{ .reg .u64 t; cvta.to.shared.u64 t, %1; cvt.u32.u64 %0, t; }"
        : "=r"(a) : "l"(p));
    return a;
}
__device__ __forceinline__ uint32_t cvt2(float hi_val, float lo_val) {
    uint32_t r;
    asm("cvt.rn.bf16x2.f32 %0, %1, %2;" : "=r"(r) : "f"(hi_val), "f"(lo_val));
    return r;
}
// split (v0,v1) into hi bf16x2 + residual-lo bf16x2 (lower lane = v0)
__device__ __forceinline__ void split2(float v0, float v1, uint32_t& h, uint32_t& l) {
    h = cvt2(v1, v0);
    float f0 = __uint_as_float(h << 16);
    float f1 = __uint_as_float(h & 0xFFFF0000u);
    l = cvt2(v1 - f1, v0 - f0);
}
__device__ __forceinline__ float lrelu(float t) { return t > 0.f ? t : 0.01f * t; }

#define LDM4(r, addr) \
    asm("ldmatrix.sync.aligned.m8n8.x4.shared.b16 {%0,%1,%2,%3}, [%4];" \
        : "=r"((r)[0]), "=r"((r)[1]), "=r"((r)[2]), "=r"((r)[3]) : "r"(addr))

#define MMA(d, a, b0_, b1_) \
    asm("mma.sync.aligned.m16n8k16.row.col.f32.bf16.bf16.f32 " \
        "{%0,%1,%2,%3},{%4,%5,%6,%7},{%8,%9},{%0,%1,%2,%3};" \
        : "+f"((d).x), "+f"((d).y), "+f"((d).z), "+f"((d).w) \
        : "r"((a)[0]), "r"((a)[1]), "r"((a)[2]), "r"((a)[3]), "r"(b0_), "r"(b1_))

// ---------------------------------------------------------------------------
// Prep: pack W1 (363x128) and W2 (128x64) into mma.sync b-fragment layout,
// bf16 hi + residual lo, zero-padded K.
// ---------------------------------------------------------------------------
__global__ void prep_k(const float* __restrict__ W1, const float* __restrict__ W2) {
    int t = blockIdx.x * 256 + threadIdx.x;
    if (t >= 12288 + 2048) return;
    if (t < 12288) {
        int lane = t & 31, ni = (t >> 5) & 15, kt = (t >> 9) & 7, chunk = t >> 12;
        int c = lane & 3, g = lane >> 2;
        int n = ni * 8 + g;
        int k0 = kt * 16 + 2 * c;
        float v00 = 0.f, v01 = 0.f, v10 = 0.f, v11 = 0.f;
        if (k0 + 1 < 121) {
            v00 = W1[(chunk * 121 + k0) * F1 + n];
            v01 = W1[(chunk * 121 + k0 + 1) * F1 + n];
        } else if (k0 < 121) {
            v00 = W1[(chunk * 121 + k0) * F1 + n];
        }
        if (k0 + 9 < 121) {
            v10 = W1[(chunk * 121 + k0 + 8) * F1 + n];
            v11 = W1[(chunk * 121 + k0 + 9) * F1 + n];
        } else if (k0 + 8 < 121) {
            v10 = W1[(chunk * 121 + k0 + 8) * F1 + n];
        }
        uint4 o;
        split2(v00, v01, o.x, o.z);
        split2(v10, v11, o.y, o.w);
        g_B1f[t] = o;
    } else {
        int t2 = t - 12288;
        int lane = t2 & 31, ni2 = (t2 >> 5) & 7, kt = t2 >> 8;
        int c = lane & 3, g = lane >> 2;
        int n = ni2 * 8 + g;
        int k0 = kt * 16 + 2 * c;
        float v00 = W2[k0 * F2 + n];
        float v01 = W2[(k0 + 1) * F2 + n];
        float v10 = W2[(k0 + 8) * F2 + n];
        float v11 = W2[(k0 + 9) * F2 + n];
        uint4 o;
        split2(v00, v01, o.x, o.z);
        split2(v10, v11, o.y, o.w);
        g_W2f[t2] = o;
    }
}

// ---------------------------------------------------------------------------
// Main: CTA = 64 px, 4 warps x 16 px. mi=1 tiles -> 128-reg budget -> 4 CTA/SM.
// ---------------------------------------------------------------------------
__global__ void __launch_bounds__(128, 4) main_k(const float* __restrict__ x,
                                                 const float* __restrict__ b1,
                                                 const float* __restrict__ b2,
                                                 const float* __restrict__ b3,
                                                 const float* __restrict__ W3,
                                                 float* __restrict__ out)
{
    extern __shared__ char smem[];
    float* sb1 = (float*)(smem + OFF_B1S);
    float* sb2 = (float*)(smem + OFF_B2S);
    float* sb3 = (float*)(smem + OFF_B3S);
    float* sW3 = (float*)(smem + OFF_W3S);

    const int tid = threadIdx.x;
    const int w = tid >> 5;
    const int lane = tid & 31;
    const int c4 = lane & 3, g = lane >> 2;
    const uint32_t sbase = smem_u32(smem);

    if (tid < F1) sb1[tid] = b1[tid];
    if (tid < F2) sb2[tid] = b2[tid];
    if (tid < F3) sb3[tid] = b3[tid];
    for (int i = tid; i < F2 * F3; i += 128) sW3[i] = W3[i];
    __syncthreads();   // only block-wide sync

    // this thread builds HALF an A row: row = tid/2, k range = (tid&1)*64..+63
    const int arow = tid >> 1;
    const int kb64 = (tid & 1) << 6;
    const int p_build = blockIdx.x * 64 + arow;
    const int pby = p_build / IW;
    const int pbx = p_build - pby * IW;

    __nv_bfloat16* rowAh = (__nv_bfloat16*)(smem + OFF_AH + arow * AROW) + kb64;
    __nv_bfloat16* rowAl = (__nv_bfloat16*)(smem + OFF_AL + arow * AROW) + kb64;

    // ldmatrix base for this lane (16-row warp tile)
    const uint32_t lm_base = sbase + OFF_AH +
        (16 * w + (lane & 15)) * AROW + (lane >> 4) * 16;

    float4 d1[16];
#pragma unroll
    for (int ni = 0; ni < 16; ni++) d1[ni] = make_float4(0.f, 0.f, 0.f, 0.f);

    // ================= layer 1: K = 3 chunks x 128 (121 valid) =============
#pragma unroll 1
    for (int chunk = 0; chunk < 3; chunk++) {
        const float* xc = x + chunk * (IH * IW);
        __syncthreads();   // prev MMAs (all warps) done with A before overwrite

        // build: k = kb64 + kk, (ki,kj) tracked incrementally
        {
            int ki = kb64 ? 5 : 0;
            int kj = kb64 ? 9 : 0;
#pragma unroll 1
            for (int kk = 0; kk < 64; kk++) {
                int kidx = kb64 + kk;
                float v = 0.f;
                if (kidx < 121) {
                    int gy = pby + ki - 5, gx = pbx + kj - 5;
                    if ((unsigned)gy < (unsigned)IH && (unsigned)gx < (unsigned)IW)
                        v = __ldg(&xc[gy * IW + gx]);
                    if (++kj == 11) { kj = 0; ki++; }
                }
                __nv_bfloat16 h = __float2bfloat16(v);
                __nv_bfloat16 l = __float2bfloat16(v - __bfloat162float(h));
                rowAh[kk] = h;
                rowAl[kk] = l;
            }
        }
        __syncthreads();

#pragma unroll 1
        for (int kt = 0; kt < 8; kt++) {
            uint32_t ah[4], al[4];
            uint32_t a0 = lm_base + kt * 32;
            LDM4(ah, a0);
            LDM4(al, a0 + (OFF_AL - OFF_AH));
            const uint4* bp = g_B1f + ((chunk * 8 + kt) * 16) * 32 + lane;
#pragma unroll
            for (int ni = 0; ni < 16; ni++) {
                uint4 bb = __ldg(bp + ni * 32);
                MMA(d1[ni], ah, bb.x, bb.y);
                MMA(d1[ni], ah, bb.z, bb.w);
                MMA(d1[ni], al, bb.x, bb.y);
            }
        }
    }

    // ============ layer 2: bias+leaky+split in regs, mma 128->64 ===========
    float4 d2[8];
#pragma unroll
    for (int ni = 0; ni < 8; ni++) d2[ni] = make_float4(0.f, 0.f, 0.f, 0.f);

#pragma unroll
    for (int kt = 0; kt < 8; kt++) {
        uint32_t ah[4], al[4];
#pragma unroll
        for (int half = 0; half < 2; half++) {
            int ni = 2 * kt + half;
            float2 bb = *(const float2*)&sb1[8 * ni + 2 * c4];
            float4 D = d1[ni];
            float v0 = lrelu(D.x + bb.x);
            float v1 = lrelu(D.y + bb.y);
            float v2 = lrelu(D.z + bb.x);
            float v3 = lrelu(D.w + bb.y);
            split2(v0, v1, ah[half * 2], al[half * 2]);
            split2(v2, v3, ah[half * 2 + 1], al[half * 2 + 1]);
        }
        const uint4* wp = g_W2f + (kt * 8) * 32 + lane;
#pragma unroll
        for (int ni = 0; ni < 8; ni++) {
            uint4 ww = __ldg(wp + ni * 32);
            MMA(d2[ni], ah, ww.x, ww.y);
            MMA(d2[ni], ah, ww.z, ww.w);
            MMA(d2[ni], al, ww.x, ww.y);
        }
    }

    // ============ h2 -> padded smem, per-pixel 64->8 + normalize ===========
    float* h2s = (float*)(smem + OFF_H2S) + w * (16 * 65);
#pragma unroll
    for (int ni = 0; ni < 8; ni++) {
        float2 bb = *(const float2*)&sb2[8 * ni + 2 * c4];
        int ch = 8 * ni + 2 * c4;
        float4 D = d2[ni];
        h2s[g * 65 + ch]           = lrelu(D.x + bb.x);
        h2s[g * 65 + ch + 1]       = lrelu(D.y + bb.y);
        h2s[(g + 8) * 65 + ch]     = lrelu(D.z + bb.x);
        h2s[(g + 8) * 65 + ch + 1] = lrelu(D.w + bb.y);
    }
    __syncwarp();

    const int lr = lane & 15;                    // pixel row within warp tile
    const float* myrow = h2s + lr * 65;
    float v[F3];
#pragma unroll
    for (int e = 0; e < F3; e++) v[e] = sb3[e];
#pragma unroll 8
    for (int k = 0; k < F2; k++) {
        float hk = myrow[k];
        const float4* wr = (const float4*)&sW3[k * F3];
        float4 w0 = wr[0], w1 = wr[1];
        v[0] += hk * w0.x; v[1] += hk * w0.y; v[2] += hk * w0.z; v[3] += hk * w0.w;
        v[4] += hk * w1.x; v[5] += hk * w1.y; v[6] += hk * w1.z; v[7] += hk * w1.w;
    }
    float ss = 0.f;
#pragma unroll
    for (int e = 0; e < F3; e++) ss += v[e] * v[e];
    float inv = 1.0f / fmaxf(sqrtf(ss), 1e-12f);

    if (lane < 16) {
        const int p = blockIdx.x * 64 + w * 16 + lr;
        float4* o = (float4*)(out + (size_t)p * F3);
        float4 o0, o1;
        o0.x = v[0] * inv; o0.y = v[1] * inv; o0.z = v[2] * inv; o0.w = v[3] * inv;
        o1.x = v[4] * inv; o1.y = v[5] * inv; o1.z = v[6] * inv; o1.w = v[7] * inv;
        o[0] = o0; o[1] = o1;
    }
}

// ---------------------------------------------------------------------------
extern "C" void kernel_launch(void* const* d_in, const int* in_sizes, int n_in,
                              void* d_out, int out_size)
{
    const float* x  = (const float*)d_in[0];
    const float* W1 = (const float*)d_in[1];
    const float* b1 = (const float*)d_in[2];
    const float* W2 = (const float*)d_in[3];
    const float* b2 = (const float*)d_in[4];
    const float* W3 = (const float*)d_in[5];
    const float* b3 = (const float*)d_in[6];
    float* out = (float*)d_out;

    prep_k<<<(12288 + 2048 + 255) / 256, 256>>>(W1, W2);

    cudaFuncSetAttribute(main_k, cudaFuncAttributeMaxDynamicSharedMemorySize,
                         SMEM_BYTES);
    main_k<<<NPIX / 64, 128, SMEM_BYTES>>>(x, b1, b2, b3, W3, out);
}

// round 7
// speedup vs baseline: 2.3688x; 2.3688x over previous
#include <cuda_runtime.h>
#include <cuda_bf16.h>
#include <cstdint>

#define IH 400
#define IW 400
#define NPIX 160000
#define F1 128
#define F2 64
#define F3 8

#define PW 416                 // padded image stride / height
#define CH (PW * PW)           // per-channel padded elems

// smem: h2 staging + small tables
#define OFF_H2S 0              // 4 warps x 32 px x 65 f32 = 33280 B
#define OFF_B1S 33280
#define OFF_B2S 33792
#define OFF_B3S 34048
#define OFF_W3S 34080
#define OFF_KOF 36128          // 64 x int2 = 512 B
#define SMEM_BYTES 36640

// padded input image, zero border: [3][416][416]
__device__ float g_xp[3 * CH];
// Pre-packed weight fragments (uint4 = {bh0,bh1,bl0,bl1} per lane)
__device__ uint4 g_B1f[3 * 8 * 16 * 32];   // [chunk][kt][ni][lane]
__device__ uint4 g_W2f[8 * 8 * 32];        // [kt][ni2][lane]

// ---------------- helpers ----------------
__device__ __forceinline__ uint32_t cvt2(float hi_val, float lo_val) {
    uint32_t r;
    asm("cvt.rn.bf16x2.f32 %0, %1, %2;" : "=r"(r) : "f"(hi_val), "f"(lo_val));
    return r;
}
// split (v0,v1) into hi bf16x2 + residual-lo bf16x2 (low half = v0)
__device__ __forceinline__ void split2(float v0, float v1, uint32_t& h, uint32_t& l) {
    h = cvt2(v1, v0);
    float f0 = __uint_as_float(h << 16);
    float f1 = __uint_as_float(h & 0xFFFF0000u);
    l = cvt2(v1 - f1, v0 - f0);
}
__device__ __forceinline__ float lrelu(float t) { return t > 0.f ? t : 0.01f * t; }

#define MMA(d, a, b0_, b1_) \
    asm("mma.sync.aligned.m16n8k16.row.col.f32.bf16.bf16.f32 " \
        "{%0,%1,%2,%3},{%4,%5,%6,%7},{%8,%9},{%0,%1,%2,%3};" \
        : "+f"((d).x), "+f"((d).y), "+f"((d).z), "+f"((d).w) \
        : "r"((a)[0]), "r"((a)[1]), "r"((a)[2]), "r"((a)[3]), "r"(b0_), "r"(b1_))

// ---------------------------------------------------------------------------
// Prep 1: pad x into g_xp (zero border, +5 offset)
// ---------------------------------------------------------------------------
__global__ void pad_k(const float* __restrict__ x) {
    int i = blockIdx.x * 256 + threadIdx.x;
    if (i >= 3 * CH) return;
    int c = i / CH, rem = i - c * CH;
    int gy = rem / PW, gx = rem - gy * PW;
    float v = 0.f;
    int sy = gy - 5, sx = gx - 5;
    if ((unsigned)sy < (unsigned)IH && (unsigned)sx < (unsigned)IW)
        v = x[(c * IH + sy) * IW + sx];
    g_xp[i] = v;
}

// ---------------------------------------------------------------------------
// Prep 2: pack W1 (363x128) and W2 (128x64) into mma.sync b-fragment layout,
// bf16 hi + residual lo, zero-padded K.
// ---------------------------------------------------------------------------
__global__ void prep_k(const float* __restrict__ W1, const float* __restrict__ W2) {
    int t = blockIdx.x * 256 + threadIdx.x;
    if (t >= 12288 + 2048) return;
    if (t < 12288) {
        int lane = t & 31, ni = (t >> 5) & 15, kt = (t >> 9) & 7, chunk = t >> 12;
        int c = lane & 3, g = lane >> 2;
        int n = ni * 8 + g;
        int k0 = kt * 16 + 2 * c;
        float v00 = 0.f, v01 = 0.f, v10 = 0.f, v11 = 0.f;
        if (k0 + 1 < 121) {
            v00 = W1[(chunk * 121 + k0) * F1 + n];
            v01 = W1[(chunk * 121 + k0 + 1) * F1 + n];
        } else if (k0 < 121) {
            v00 = W1[(chunk * 121 + k0) * F1 + n];
        }
        if (k0 + 9 < 121) {
            v10 = W1[(chunk * 121 + k0 + 8) * F1 + n];
            v11 = W1[(chunk * 121 + k0 + 9) * F1 + n];
        } else if (k0 + 8 < 121) {
            v10 = W1[(chunk * 121 + k0 + 8) * F1 + n];
        }
        uint4 o;
        split2(v00, v01, o.x, o.z);
        split2(v10, v11, o.y, o.w);
        g_B1f[t] = o;
    } else {
        int t2 = t - 12288;
        int lane = t2 & 31, ni2 = (t2 >> 5) & 7, kt = t2 >> 8;
        int c = lane & 3, g = lane >> 2;
        int n = ni2 * 8 + g;
        int k0 = kt * 16 + 2 * c;
        float v00 = W2[k0 * F2 + n];
        float v01 = W2[(k0 + 1) * F2 + n];
        float v10 = W2[(k0 + 8) * F2 + n];
        float v11 = W2[(k0 + 9) * F2 + n];
        uint4 o;
        split2(v00, v01, o.x, o.z);
        split2(v10, v11, o.y, o.w);
        g_W2f[t2] = o;
    }
}

// ---------------------------------------------------------------------------
// Main: CTA = 128 px, 4 warps x 32 px (R4 tiling). A fragments built DIRECTLY
// in registers from the padded image: no A smem, no ldmatrix, no chunk syncs.
// ---------------------------------------------------------------------------
__global__ void __launch_bounds__(128) main_k(const float* __restrict__ b1,
                                              const float* __restrict__ b2,
                                              const float* __restrict__ b3,
                                              const float* __restrict__ W3,
                                              float* __restrict__ out)
{
    extern __shared__ char smem[];
    float* sb1 = (float*)(smem + OFF_B1S);
    float* sb2 = (float*)(smem + OFF_B2S);
    float* sb3 = (float*)(smem + OFF_B3S);
    float* sW3 = (float*)(smem + OFF_W3S);
    int2*  kof = (int2*)(smem + OFF_KOF);

    const int tid = threadIdx.x;
    const int w = tid >> 5;
    const int lane = tid & 31;
    const int c4 = lane & 3, g = lane >> 2;

    if (tid < F1) sb1[tid] = b1[tid];
    if (tid < F2) sb2[tid] = b2[tid];
    if (tid < F3) sb3[tid] = b3[tid];
    for (int i = tid; i < F2 * F3; i += 128) sW3[i] = W3[i];
    if (tid < 64) {                       // k -> padded-image offset table
        int k0 = 2 * tid, k1 = 2 * tid + 1;
        kof[tid] = make_int2((k0 / 11) * PW + (k0 % 11),
                             (k1 / 11) * PW + (k1 % 11));
    }
    __syncthreads();   // only block-wide sync

    // 4 pixel base offsets for this lane: rows g, g+8 in mi=0 / mi=1 tiles
    int pbase[2][2];
#pragma unroll
    for (int mi = 0; mi < 2; mi++)
#pragma unroll
        for (int rr = 0; rr < 2; rr++) {
            int p = blockIdx.x * 128 + w * 32 + mi * 16 + rr * 8 + g;
            int py = p / IW;
            pbase[mi][rr] = py * PW + (p - py * IW);
        }

    float4 d1[2][16];
#pragma unroll
    for (int mi = 0; mi < 2; mi++)
#pragma unroll
        for (int ni = 0; ni < 16; ni++) d1[mi][ni] = make_float4(0.f, 0.f, 0.f, 0.f);

    // ================= layer 1: K = 3 chunks x 128 (121 valid) =============
#pragma unroll 1
    for (int chunk = 0; chunk < 3; chunk++) {
        const float* xc = g_xp + chunk * CH;

#pragma unroll 1
        for (int kt = 0; kt < 8; kt++) {
            uint32_t ah[2][4], al[2][4];
#pragma unroll
            for (int j = 0; j < 2; j++) {
                int2 off = kof[kt * 8 + c4 + 4 * j];
#pragma unroll
                for (int mi = 0; mi < 2; mi++) {
                    float v00 = __ldg(xc + pbase[mi][0] + off.x);
                    float v01 = __ldg(xc + pbase[mi][0] + off.y);
                    float v10 = __ldg(xc + pbase[mi][1] + off.x);
                    float v11 = __ldg(xc + pbase[mi][1] + off.y);
                    split2(v00, v01, ah[mi][2 * j],     al[mi][2 * j]);
                    split2(v10, v11, ah[mi][2 * j + 1], al[mi][2 * j + 1]);
                }
            }
            const uint4* bp = g_B1f + ((chunk * 8 + kt) * 16) * 32 + lane;
#pragma unroll
            for (int ni = 0; ni < 16; ni++) {
                uint4 bb = __ldg(bp + ni * 32);
                MMA(d1[0][ni], ah[0], bb.x, bb.y);
                MMA(d1[1][ni], ah[1], bb.x, bb.y);
                MMA(d1[0][ni], ah[0], bb.z, bb.w);
                MMA(d1[1][ni], ah[1], bb.z, bb.w);
                MMA(d1[0][ni], al[0], bb.x, bb.y);
                MMA(d1[1][ni], al[1], bb.x, bb.y);
            }
        }
    }

    // ============ layer 2: bias+leaky+split in regs, mma 128->64 ===========
    float4 d2[2][8];
#pragma unroll
    for (int mi = 0; mi < 2; mi++)
#pragma unroll
        for (int ni = 0; ni < 8; ni++) d2[mi][ni] = make_float4(0.f, 0.f, 0.f, 0.f);

#pragma unroll
    for (int kt = 0; kt < 8; kt++) {
        uint32_t ah[2][4], al[2][4];
#pragma unroll
        for (int half = 0; half < 2; half++) {
            int ni = 2 * kt + half;
            float2 bb = *(const float2*)&sb1[8 * ni + 2 * c4];
#pragma unroll
            for (int mi = 0; mi < 2; mi++) {
                float4 D = d1[mi][ni];
                float v0 = lrelu(D.x + bb.x);
                float v1 = lrelu(D.y + bb.y);
                float v2 = lrelu(D.z + bb.x);
                float v3 = lrelu(D.w + bb.y);
                split2(v0, v1, ah[mi][half * 2], al[mi][half * 2]);
                split2(v2, v3, ah[mi][half * 2 + 1], al[mi][half * 2 + 1]);
            }
        }
        const uint4* wp = g_W2f + (kt * 8) * 32 + lane;
#pragma unroll
        for (int ni = 0; ni < 8; ni++) {
            uint4 ww = __ldg(wp + ni * 32);
            MMA(d2[0][ni], ah[0], ww.x, ww.y);
            MMA(d2[1][ni], ah[1], ww.x, ww.y);
            MMA(d2[0][ni], ah[0], ww.z, ww.w);
            MMA(d2[1][ni], ah[1], ww.z, ww.w);
            MMA(d2[0][ni], al[0], ww.x, ww.y);
            MMA(d2[1][ni], al[1], ww.x, ww.y);
        }
    }

    // ============ h2 -> padded smem, per-pixel 64->8 + normalize ===========
    float* h2s = (float*)(smem + OFF_H2S) + w * (32 * 65);
#pragma unroll
    for (int ni = 0; ni < 8; ni++) {
        float2 bb = *(const float2*)&sb2[8 * ni + 2 * c4];
        int ch = 8 * ni + 2 * c4;
#pragma unroll
        for (int mi = 0; mi < 2; mi++) {
            float4 D = d2[mi][ni];
            int r0 = 16 * mi + g;
            h2s[r0 * 65 + ch]           = lrelu(D.x + bb.x);
            h2s[r0 * 65 + ch + 1]       = lrelu(D.y + bb.y);
            h2s[(r0 + 8) * 65 + ch]     = lrelu(D.z + bb.x);
            h2s[(r0 + 8) * 65 + ch + 1] = lrelu(D.w + bb.y);
        }
    }
    __syncwarp();

    const float* myrow = h2s + lane * 65;
    float v[F3];
#pragma unroll
    for (int e = 0; e < F3; e++) v[e] = sb3[e];
#pragma unroll 8
    for (int k = 0; k < F2; k++) {
        float hk = myrow[k];
        const float4* wr = (const float4*)&sW3[k * F3];
        float4 w0 = wr[0], w1 = wr[1];
        v[0] += hk * w0.x; v[1] += hk * w0.y; v[2] += hk * w0.z; v[3] += hk * w0.w;
        v[4] += hk * w1.x; v[5] += hk * w1.y; v[6] += hk * w1.z; v[7] += hk * w1.w;
    }
    float ss = 0.f;
#pragma unroll
    for (int e = 0; e < F3; e++) ss += v[e] * v[e];
    float inv = 1.0f / fmaxf(sqrtf(ss), 1e-12f);

    const int p = blockIdx.x * 128 + w * 32 + lane;
    float4* o = (float4*)(out + (size_t)p * F3);
    float4 o0, o1;
    o0.x = v[0] * inv; o0.y = v[1] * inv; o0.z = v[2] * inv; o0.w = v[3] * inv;
    o1.x = v[4] * inv; o1.y = v[5] * inv; o1.z = v[6] * inv; o1.w = v[7] * inv;
    o[0] = o0; o[1] = o1;
}

// ---------------------------------------------------------------------------
extern "C" void kernel_launch(void* const* d_in, const int* in_sizes, int n_in,
                              void* d_out, int out_size)
{
    const float* x  = (const float*)d_in[0];
    const float* W1 = (const float*)d_in[1];
    const float* b1 = (const float*)d_in[2];
    const float* W2 = (const float*)d_in[3];
    const float* b2 = (const float*)d_in[4];
    const float* W3 = (const float*)d_in[5];
    const float* b3 = (const float*)d_in[6];
    float* out = (float*)d_out;

    pad_k<<<(3 * CH + 255) / 256, 256>>>(x);
    prep_k<<<(12288 + 2048 + 255) / 256, 256>>>(W1, W2);

    cudaFuncSetAttribute(main_k, cudaFuncAttributeMaxDynamicSharedMemorySize,
                         SMEM_BYTES);
    main_k<<<NPIX / 128, 128, SMEM_BYTES>>>(b1, b2, b3, W3, out);
}